// round 13
// baseline (speedup 1.0000x reference)
#include <cuda_runtime.h>
#include <cuda_bf16.h>
#include <cstdint>

#define BB      32768
#define HD      256
#define MT      128              // batch rows per CTA
#define KC      64               // K elems per chunk
#define NCHUNK  8                // 512/64
#define NT      512              // threads

// stage layout (bytes): Ah[16K] Al[16K] Bh[32K] Bl[32K]
#define AH_OFF  0
#define AL_OFF  16384
#define BH_OFF  32768
#define BL_OFF  65536
#define STAGE   98304
#define SMEM_DYN (2*STAGE + 1024)

// ---- device scratch (allocation-free rule: __device__ globals) ----
__device__ unsigned char g_Bh[3][262144];        // pre-swizzled B^T hi: [wr, wz, [whx;whh]]
__device__ unsigned char g_Bl[3][262144];        // lo parts
__device__ unsigned char g_Ah[256][8][16384];    // split [x|h] hi, swizzled, per tile/chunk
__device__ unsigned char g_Al[256][8][16384];    // lo
__device__ unsigned char g_RHh[256][4][16384];   // split r*h hi, swizzled
__device__ unsigned char g_RHl[256][4][16384];   // lo
__device__ float g_z[(size_t)BB * HD];           // z gate (fp32)

// ================= helpers =================
static __device__ __forceinline__ unsigned sm_u32(const void* p) {
    unsigned a;
    asm("{.reg .u64 t; cvta.to.shared.u64 t, %1; cvt.u32.u64 %0, t;}" : "=r"(a) : "l"(p));
    return a;
}
static __device__ __forceinline__ void ldsm4(unsigned* r, unsigned addr) {
    asm volatile("ldmatrix.sync.aligned.m8n8.x4.shared.b16 {%0,%1,%2,%3}, [%4];"
                 : "=r"(r[0]), "=r"(r[1]), "=r"(r[2]), "=r"(r[3]) : "r"(addr));
}
static __device__ __forceinline__ void mma16816(float* c, const unsigned* a, const unsigned* b) {
    asm volatile("mma.sync.aligned.m16n8k16.row.col.f32.bf16.bf16.f32 "
                 "{%0,%1,%2,%3}, {%4,%5,%6,%7}, {%8,%9}, {%0,%1,%2,%3};"
                 : "+f"(c[0]), "+f"(c[1]), "+f"(c[2]), "+f"(c[3])
                 : "r"(a[0]), "r"(a[1]), "r"(a[2]), "r"(a[3]), "r"(b[0]), "r"(b[1]));
}
static __device__ __forceinline__ void cpa16(unsigned dst, const void* src) {
    asm volatile("cp.async.cg.shared.global [%0], [%1], 16;" :: "r"(dst), "l"(src));
}
#define CP_COMMIT() asm volatile("cp.async.commit_group;")
#define CP_WAIT0()  asm volatile("cp.async.wait_group 0;")

static __device__ __forceinline__ unsigned pkbf(float a, float b) {
    __nv_bfloat162 t = __halves2bfloat162(__float2bfloat16(a), __float2bfloat16(b));
    return *reinterpret_cast<unsigned*>(&t);
}
static __device__ __forceinline__ float bferr(float v) {   // v - bf16(v)
    return v - __bfloat162float(__float2bfloat16(v));
}
static __device__ __forceinline__ float sig(float v) { return 1.0f / (1.0f + __expf(-v)); }

// ================= prep: transpose + split + swizzle weights =================
// Per matrix, per k-chunk c (8 chunks of 64 k): region c*32768 bytes, inside:
//   offset(n, kloc) = n*128 + ((kloc*2) ^ ((n&7)<<4))
__global__ void __launch_bounds__(64)
prep_w(const float* __restrict__ wr, const float* __restrict__ wz,
       const float* __restrict__ whx, const float* __restrict__ whh)
{
    int k = blockIdx.x, mat = blockIdx.y, n4 = threadIdx.x * 4;
    const float* row = (mat == 0) ? wr + k * HD
                     : (mat == 1) ? wz + k * HD
                     : (k < 256 ? whx + k * HD : whh + (k - 256) * HD);
    float4 v = *(const float4*)(row + n4);
    float vv[4] = {v.x, v.y, v.z, v.w};
    unsigned reg = (unsigned)(k >> 6) * 32768u;
    unsigned kb  = (unsigned)(k & 63) * 2u;
    #pragma unroll
    for (int j = 0; j < 4; j++) {
        int n = n4 + j;
        unsigned off = reg + (unsigned)n * 128u + (kb ^ (((unsigned)n & 7u) << 4));
        __nv_bfloat16 h = __float2bfloat16(vv[j]);
        *(unsigned short*)(g_Bh[mat] + off) = __bfloat16_as_ushort(h);
        *(unsigned short*)(g_Bl[mat] + off) =
            __bfloat16_as_ushort(__float2bfloat16(vv[j] - __bfloat162float(h)));
    }
}

// ================= fused GRU via mma.sync bf16 (3-pass split) =================
__global__ void __launch_bounds__(NT, 1)
gru_hmma(const float* __restrict__ x,  const float* __restrict__ hp,
         const float* __restrict__ br, const float* __restrict__ bz,
         const float* __restrict__ bh, float* __restrict__ out)
{
    extern __shared__ char dynsm[];
    unsigned raw   = sm_u32(dynsm);
    unsigned abase = (raw + 1023u) & ~1023u;
    char*    smb   = dynsm + (abase - raw);

    const int tid  = threadIdx.x;
    const int lane = tid & 31;
    const int wid  = tid >> 5;
    const int wm   = wid & 3;               // m block (32 rows)
    const int wn   = wid >> 2;              // n block (64 cols)
    const int tile = blockIdx.x;
    const int row0 = tile * MT;

    // ldmatrix per-lane geometry
    const int      mA0    = wm * 32 + (lane & 15);
    const unsigned aklane = (unsigned)(lane >> 4) * 16u;
    const int      nB     = wn * 64 + ((lane >> 4) << 3) + (lane & 7);
    const unsigned bklane = (unsigned)((lane >> 3) & 1) * 16u;
    const unsigned xs     = ((unsigned)(lane & 7)) << 4;

    // epilogue geometry
    const int emr = wm * 32 + (lane >> 2);                   // + mi*16 + half*8 (local row)
    const int enc = wn * 64 + (lane & 3) * 2;                // + nb*8

    float acc[2][8][4];

    #pragma unroll 1
    for (int pass = 0; pass < 3; pass++) {
        const unsigned char* gBh = g_Bh[pass];
        const unsigned char* gBl = g_Bl[pass];

        #pragma unroll
        for (int mi = 0; mi < 2; mi++)
            #pragma unroll
            for (int nb = 0; nb < 8; nb++)
                #pragma unroll
                for (int q = 0; q < 4; q++) acc[mi][nb][q] = 0.0f;

        // ---- staging helpers ----
        auto stageB = [&](int c, int buf) {
            unsigned bb = abase + buf * STAGE;
            const unsigned char* sH = gBh + (size_t)c * 32768;
            const unsigned char* sL = gBl + (size_t)c * 32768;
            #pragma unroll
            for (int q = 0; q < 4; q++) {
                int i = tid + q * NT;
                cpa16(bb + BH_OFF + i * 16, sH + i * 16);
                cpa16(bb + BL_OFF + i * 16, sL + i * 16);
            }
        };
        // pass 1/2: A via cp.async from pre-split buffers
        auto stageA_cp = [&](int c, int buf) {
            unsigned bb = abase + buf * STAGE;
            const unsigned char *aH, *aL;
            if (pass == 1 || c < 4) { aH = g_Ah[tile][c];     aL = g_Al[tile][c]; }
            else                    { aH = g_RHh[tile][c - 4]; aL = g_RHl[tile][c - 4]; }
            #pragma unroll
            for (int q = 0; q < 2; q++) {
                int i = tid + q * NT;
                cpa16(bb + AH_OFF + i * 16, aH + i * 16);
                cpa16(bb + AL_OFF + i * 16, aL + i * 16);
            }
        };
        // pass 0: LDG fp32 -> split -> swizzled STS + write-through STG
        float4 pf[4];
        auto ldgA = [&](int c) {
            const float* src = (c < 4) ? x + (size_t)row0 * HD + c * KC
                                       : hp + (size_t)row0 * HD + (c - 4) * KC;
            #pragma unroll
            for (int q = 0; q < 4; q++) {
                int i = tid + q * NT;
                int m = i >> 4, k4 = (i & 15) << 2;
                pf[q] = *(const float4*)(src + (size_t)m * HD + k4);
            }
        };
        auto stsA_wt = [&](int c, int buf) {
            #pragma unroll
            for (int q = 0; q < 4; q++) {
                int i = tid + q * NT;
                int m = i >> 4;
                unsigned kb = (unsigned)(i & 15) << 3;            // bytes
                unsigned o  = (unsigned)m * 128u + (kb ^ (((unsigned)m & 7u) << 4));
                char* base = smb + buf * STAGE;
                float4 v = pf[q];
                uint2 hv = make_uint2(pkbf(v.x, v.y), pkbf(v.z, v.w));
                uint2 lv = make_uint2(pkbf(bferr(v.x), bferr(v.y)),
                                      pkbf(bferr(v.z), bferr(v.w)));
                *(uint2*)(base + AH_OFF + o) = hv;
                *(uint2*)(base + AL_OFF + o) = lv;
                *(uint2*)(g_Ah[tile][c] + o) = hv;      // write-through for passes 1,2
                *(uint2*)(g_Al[tile][c] + o) = lv;
            }
        };
        auto compute = [&](int buf) {
            unsigned bb    = abase + buf * STAGE;
            unsigned aAddr = bb + (unsigned)mA0 * 128u;
            unsigned bAddr = bb + BH_OFF + (unsigned)nB * 128u;
            #pragma unroll
            for (int ks = 0; ks < 4; ks++) {
                unsigned aoff = ((unsigned)ks * 32u + aklane) ^ xs;
                unsigned ah0[4], ah1[4], al0[4], al1[4];
                ldsm4(ah0, aAddr + AH_OFF + aoff);
                ldsm4(ah1, aAddr + AH_OFF + 2048u + aoff);
                ldsm4(al0, aAddr + AL_OFF + aoff);
                ldsm4(al1, aAddr + AL_OFF + 2048u + aoff);
                unsigned boff = ((unsigned)ks * 32u + bklane) ^ xs;
                #pragma unroll
                for (int p = 0; p < 4; p++) {
                    unsigned bhv[4], blv[4];
                    unsigned ba = bAddr + (unsigned)p * 2048u + boff;
                    ldsm4(bhv, ba);
                    ldsm4(blv, ba + (BL_OFF - BH_OFF));
                    mma16816(acc[0][2*p],   ah0, bhv);     mma16816(acc[1][2*p],   ah1, bhv);
                    mma16816(acc[0][2*p+1], ah0, bhv + 2); mma16816(acc[1][2*p+1], ah1, bhv + 2);
                    mma16816(acc[0][2*p],   ah0, blv);     mma16816(acc[1][2*p],   ah1, blv);
                    mma16816(acc[0][2*p+1], ah0, blv + 2); mma16816(acc[1][2*p+1], ah1, blv + 2);
                    mma16816(acc[0][2*p],   al0, bhv);     mma16816(acc[1][2*p],   al1, bhv);
                    mma16816(acc[0][2*p+1], al0, bhv + 2); mma16816(acc[1][2*p+1], al1, bhv + 2);
                }
            }
        };

        // ---- K pipeline: double-buffered chunks ----
        if (pass == 0) {
            stageB(0, 0); CP_COMMIT();
            ldgA(0);
            stsA_wt(0, 0);
            CP_WAIT0();
            __syncthreads();
            #pragma unroll 1
            for (int c = 0; c < NCHUNK; c++) {
                int buf = c & 1;
                if (c < NCHUNK - 1) { stageB(c + 1, buf ^ 1); CP_COMMIT(); ldgA(c + 1); }
                compute(buf);
                if (c < NCHUNK - 1) { stsA_wt(c + 1, buf ^ 1); CP_WAIT0(); }
                __syncthreads();
            }
        } else {
            stageA_cp(0, 0); stageB(0, 0); CP_COMMIT();
            CP_WAIT0();
            __syncthreads();
            #pragma unroll 1
            for (int c = 0; c < NCHUNK; c++) {
                int buf = c & 1;
                if (c < NCHUNK - 1) { stageA_cp(c + 1, buf ^ 1); stageB(c + 1, buf ^ 1); CP_COMMIT(); }
                compute(buf);
                CP_WAIT0();
                __syncthreads();
            }
        }

        // ---- epilogue ----
        #pragma unroll
        for (int nb = 0; nb < 8; nb++) {
            int col = enc + nb * 8;
            float2 b2;
            if (pass == 0)      b2 = *(const float2*)&br[col];
            else if (pass == 1) b2 = *(const float2*)&bz[col];
            else                b2 = *(const float2*)&bh[col];
            #pragma unroll
            for (int mi = 0; mi < 2; mi++)
                #pragma unroll
                for (int hf = 0; hf < 2; hf++) {
                    int ml  = emr + mi * 16 + hf * 8;         // local row
                    size_t go = (size_t)(row0 + ml) * HD + col;
                    float v0 = acc[mi][nb][hf * 2 + 0] + b2.x;
                    float v1 = acc[mi][nb][hf * 2 + 1] + b2.y;
                    if (pass == 0) {
                        float2 h2 = *(const float2*)(hp + go);
                        float rh0 = sig(v0) * h2.x, rh1 = sig(v1) * h2.y;
                        int cc = col >> 6, kl = col & 63;
                        unsigned o = (unsigned)ml * 128u +
                                     (((unsigned)kl * 2u) ^ (((unsigned)ml & 7u) << 4));
                        *(unsigned*)(g_RHh[tile][cc] + o) = pkbf(rh0, rh1);
                        *(unsigned*)(g_RHl[tile][cc] + o) = pkbf(bferr(rh0), bferr(rh1));
                    } else if (pass == 1) {
                        *(float2*)(g_z + go) = make_float2(sig(v0), sig(v1));
                    } else {
                        float g0 = tanhf(v0), g1 = tanhf(v1);
                        float2 h2 = *(const float2*)(hp + go);
                        float2 z2 = *(const float2*)(g_z + go);
                        *(float2*)(out + go) = make_float2(h2.x + z2.x * (g0 - h2.x),
                                                           h2.y + z2.y * (g1 - h2.y));
                    }
                }
        }
        __syncthreads();
    }
}

// ================= launch =================
extern "C" void kernel_launch(void* const* d_in, const int* in_sizes, int n_in,
                              void* d_out, int out_size)
{
    const float* x   = (const float*)d_in[0];
    const float* hp  = (const float*)d_in[1];
    const float* wr  = (const float*)d_in[2];
    const float* wz  = (const float*)d_in[3];
    const float* whh = (const float*)d_in[4];
    const float* whx = (const float*)d_in[5];
    const float* br  = (const float*)d_in[6];
    const float* bz  = (const float*)d_in[7];
    const float* bh  = (const float*)d_in[8];

    cudaFuncSetAttribute(gru_hmma, cudaFuncAttributeMaxDynamicSharedMemorySize, SMEM_DYN);

    prep_w<<<dim3(512, 3), 64>>>(wr, wz, whx, whh);
    gru_hmma<<<BB / MT, NT, SMEM_DYN>>>(x, hp, br, bz, bh, (float*)d_out);
}